// round 11
// baseline (speedup 1.0000x reference)
#include <cuda_runtime.h>
#include <cuda_bf16.h>
#include <cstdint>

// Embedding gather: out[r, :] = table[indices[r], :]
// n_rows = B*F = 819200, D = 64 floats (256 B per row).
//
// R10: persistent grid-stride variant of the converged R9 config.
// Same proven structure (16 float4 lanes/row, RPT=8 front-batched
// independent gathers, BLOCK=512, u32 math, .cs streaming stores), but
// each block loops over tiles instead of one-shot: removes per-block
// cold-start latency behind CLC dispatch and lets the compiler overlap
// tile t's stores with tile t+1's loads (stores never block), keeping
// MLP sustained across tile boundaries.

static constexpr int D      = 64;           // embedding dim (floats)
static constexpr int LANES  = 16;           // float4 lanes per row
static constexpr int RPT    = 8;            // rows per thread
static constexpr int BLOCK  = 512;
static constexpr int GROUPS = BLOCK / LANES;              // 32 row-groups
static constexpr int ROWS_PER_TILE = GROUPS * RPT;        // 256

__global__ __launch_bounds__(BLOCK)
void gather_kernel(const int* __restrict__ indices,
                   const float4* __restrict__ table4,
                   float4* __restrict__ out4,
                   unsigned n_tiles, unsigned n_rows)
{
    const unsigned local_row = threadIdx.x >> 4;   // 0..31
    const unsigned lane      = threadIdx.x & 15u;  // 0..15

    for (unsigned t = blockIdx.x; t < n_tiles; t += gridDim.x) {
        const unsigned row_base = t * (unsigned)ROWS_PER_TILE + local_row;

        unsigned idx[RPT];
        float4   vals[RPT];

        // Phase 1: batched independent index loads
#pragma unroll
        for (int k = 0; k < RPT; k++) {
            const unsigned r = row_base + k * GROUPS;
            idx[k] = (r < n_rows) ? (unsigned)__ldg(indices + r) : 0u;
        }

        // Phase 2: batched independent table gathers (MLP = RPT)
#pragma unroll
        for (int k = 0; k < RPT; k++)
            vals[k] = __ldg(table4 + idx[k] * (unsigned)(D / 4) + lane);

        // Phase 3: streaming stores (evict-first; output is write-once)
#pragma unroll
        for (int k = 0; k < RPT; k++) {
            const unsigned r = row_base + k * GROUPS;
            if (r < n_rows)
                __stcs(out4 + r * (unsigned)(D / 4) + lane, vals[k]);
        }
    }
}

extern "C" void kernel_launch(void* const* d_in, const int* in_sizes, int n_in,
                              void* d_out, int out_size)
{
    const int*    indices = (const int*)d_in[0];
    const float4* table4  = (const float4*)d_in[1];
    float4*       out4    = (float4*)d_out;

    const unsigned n_rows  = (unsigned)in_sizes[0];   // 819200
    const unsigned n_tiles = (n_rows + ROWS_PER_TILE - 1) / ROWS_PER_TILE;  // 3200

    // Persistent grid: ~3 resident CTAs/SM at 512 thr, 32 regs -> 148*3.
    unsigned grid = 148u * 3u;
    if (grid > n_tiles) grid = n_tiles;

    gather_kernel<<<grid, BLOCK>>>(indices, table4, out4, n_tiles, n_rows);
}

// round 12
// speedup vs baseline: 1.0874x; 1.0874x over previous
#include <cuda_runtime.h>
#include <cuda_bf16.h>
#include <cstdint>

// Embedding gather: out[r, :] = table[indices[r], :]
// n_rows = B*F = 819200, D = 64 floats (256 B per row).
//
// FINAL (R11 = R9 config, best measured kernel time 57.86us, DRAM 73%).
//
// Convergence evidence: 11 structural variants (reg-MLP 1/4/8, cp.async
// burst, barrier-free cp.async pipeline, evict_last, L1-bypass .cg, u32
// addressing, BLOCK 256/512, persistent grid) all land at 57.8-59.7us
// with DRAM traffic at the byte floor (~333 MB = 143 MB unique table
// reads + 210 MB streaming writes + 3 MB indices, L2 absorbing duplicate
// reads). ~72% DRAM SOL is the HBM efficiency ceiling for interleaved
// random-256B gathers + streaming writes on sm_103a; MLP, occupancy,
// issue path, L1/L2 policy, and launch shape are all non-binding.
//
// Structure: 16 float4 lanes per row, RPT=8 front-batched independent
// gathers per thread, 512-thread CTAs, u32 address math, exact-tile
// main kernel (no predicates) + guarded tail, .cs streaming stores.

static constexpr int D      = 64;           // embedding dim (floats)
static constexpr int LANES  = 16;           // float4 lanes per row
static constexpr int RPT    = 8;            // rows per thread
static constexpr int BLOCK  = 512;
static constexpr int GROUPS = BLOCK / LANES;              // 32 row-groups
static constexpr int ROWS_PER_BLOCK = GROUPS * RPT;       // 256

__global__ __launch_bounds__(BLOCK)
void gather_main(const int* __restrict__ indices,
                 const float4* __restrict__ table4,
                 float4* __restrict__ out4)
{
    const unsigned local_row = threadIdx.x >> 4;   // 0..31
    const unsigned lane      = threadIdx.x & 15u;  // 0..15
    const unsigned row_base  = blockIdx.x * (unsigned)ROWS_PER_BLOCK + local_row;

    unsigned idx[RPT];
    float4   vals[RPT];

    // Phase 1: batched independent index loads (L1-broadcast across lanes)
#pragma unroll
    for (int k = 0; k < RPT; k++)
        idx[k] = (unsigned)__ldg(indices + row_base + k * GROUPS);

    // Phase 2: batched independent table gathers (MLP = RPT)
#pragma unroll
    for (int k = 0; k < RPT; k++)
        vals[k] = __ldg(table4 + idx[k] * (unsigned)(D / 4) + lane);

    // Phase 3: streaming stores (evict-first; output is write-once)
#pragma unroll
    for (int k = 0; k < RPT; k++)
        __stcs(out4 + (row_base + k * GROUPS) * (unsigned)(D / 4) + lane, vals[k]);
}

__global__ __launch_bounds__(BLOCK)
void gather_tail(const int* __restrict__ indices,
                 const float4* __restrict__ table4,
                 float4* __restrict__ out4,
                 unsigned row_start, unsigned n_rows)
{
    const unsigned row  = row_start + blockIdx.x * GROUPS + (threadIdx.x >> 4);
    const unsigned lane = threadIdx.x & 15u;
    if (row >= n_rows) return;
    const unsigned idx = (unsigned)__ldg(indices + row);
    __stcs(out4 + row * (unsigned)(D / 4) + lane,
           __ldg(table4 + idx * (unsigned)(D / 4) + lane));
}

extern "C" void kernel_launch(void* const* d_in, const int* in_sizes, int n_in,
                              void* d_out, int out_size)
{
    const int*    indices = (const int*)d_in[0];
    const float4* table4  = (const float4*)d_in[1];
    float4*       out4    = (float4*)d_out;

    const unsigned n_rows    = (unsigned)in_sizes[0];          // 819200
    const unsigned full_blks = n_rows / ROWS_PER_BLOCK;        // 3200 (exact)
    const unsigned done      = full_blks * ROWS_PER_BLOCK;

    if (full_blks)
        gather_main<<<full_blks, BLOCK>>>(indices, table4, out4);

    if (done < n_rows) {
        const unsigned rem  = n_rows - done;
        const unsigned blks = (rem * LANES + BLOCK - 1) / BLOCK;
        gather_tail<<<blks, BLOCK>>>(indices, table4, out4, done, n_rows);
    }
}